// round 12
// baseline (speedup 1.0000x reference)
#include <cuda_runtime.h>
#include <math.h>
#include <stdint.h>

// ---------------- problem constants ----------------
#define Mn    200
#define Sn    20
#define Hn    3
#define Cn    100
#define Ln    5
#define HIDn  150
#define Bn    128
#define En    3200
#define Kn    160
#define ETOT  3400          // E + M self loops
#define OBSD  9002
#define PASTD 277
#define HC    300           // H*C
#define D2IN  49600
#define GDIM  600           // 4*HID
#define SPLITK 148
#define CHUNKK 336          // 148*336 = 49728 >= 49600
#define NRECB 80            // recurrence blocks (one wave)
#define XLD   101           // smem row stride (odd -> low bank conflicts)

// ---------------- scratch (device globals, allocation-free) ----------------
__device__ float g_gx[1280 * GDIM];
__device__ float g_h[2 * Bn * HIDn];
__device__ float g_c[2 * Bn * HIDn];
__device__ float g_gates[2 * Bn * GDIM];
__device__ float g_feat[Bn * Mn * 42];
__device__ float g_xl[Bn * Mn * HC];
__device__ float g_xr[Bn * Mn * HC];
__device__ float g_gatout[Bn * Mn * HC];
__device__ int   g_coff[Mn + 1];
__device__ int   g_csrc[ETOT];
__device__ float g_concat[Bn * D2IN];
__device__ float g_partial[SPLITK * 128 * 128];
__device__ float g_hidden[Bn * 128];
__device__ unsigned g_barc = 0;     // monotonic grid-barrier counter (replay-safe)

// ---------------- helpers ----------------
__device__ __forceinline__ float sigf(float x) { return 1.0f / (1.0f + expf(-x)); }

// Monotonic grid barrier: each of the NRECB blocks arrives once; barrier
// completes when the counter reaches the next multiple of NRECB. Counter never
// resets -> safe across graph replays.
__device__ __forceinline__ void gbar()
{
    __syncthreads();
    __threadfence();
    if (threadIdx.x == 0) {
        unsigned v = atomicAdd(&g_barc, 1u);
        unsigned target = (v / (unsigned)NRECB + 1u) * (unsigned)NRECB;
        while (atomicAdd(&g_barc, 0u) < target) __nanosleep(64);
    }
    __syncthreads();
}

// ---------------- generic tiled GEMM: C = act(A@B + bias1 + bias2) ----------------
__global__ void gemm_bias_act(const float* __restrict__ A, int lda,
                              const float* __restrict__ B, int ldb,
                              float* __restrict__ C, int ldc,
                              const float* __restrict__ bias1,
                              const float* __restrict__ bias2,
                              int Mr, int N, int Kd, int act, float slope)
{
    __shared__ float As[16][68];
    __shared__ float Bs[16][64];
    const int tid = threadIdx.x;
    const int m0 = blockIdx.y * 64;
    const int n0 = blockIdx.x * 64;
    const int tx = tid & 15;
    const int ty = tid >> 4;
    float acc[4][4] = {};

    for (int k0 = 0; k0 < Kd; k0 += 16) {
        {
            int ka = k0 + tx;
            #pragma unroll
            for (int it = 0; it < 4; it++) {
                int m = ty + 16 * it;
                int gm = m0 + m;
                float v = 0.0f;
                if (gm < Mr && ka < Kd) v = A[(size_t)gm * lda + ka];
                As[tx][m] = v;
            }
        }
        {
            int c = tid & 63;
            int kb = tid >> 6;
            #pragma unroll
            for (int it = 0; it < 4; it++) {
                int kk = kb + 4 * it;
                int gk = k0 + kk;
                float v = 0.0f;
                if (gk < Kd && (n0 + c) < N) v = B[(size_t)gk * ldb + n0 + c];
                Bs[kk][c] = v;
            }
        }
        __syncthreads();
        #pragma unroll
        for (int k = 0; k < 16; k++) {
            float4 a = *(const float4*)&As[k][ty * 4];
            float4 b = *(const float4*)&Bs[k][tx * 4];
            acc[0][0] += a.x * b.x; acc[0][1] += a.x * b.y; acc[0][2] += a.x * b.z; acc[0][3] += a.x * b.w;
            acc[1][0] += a.y * b.x; acc[1][1] += a.y * b.y; acc[1][2] += a.y * b.z; acc[1][3] += a.y * b.w;
            acc[2][0] += a.z * b.x; acc[2][1] += a.z * b.y; acc[2][2] += a.z * b.z; acc[2][3] += a.z * b.w;
            acc[3][0] += a.w * b.x; acc[3][1] += a.w * b.y; acc[3][2] += a.w * b.z; acc[3][3] += a.w * b.w;
        }
        __syncthreads();
    }

    #pragma unroll
    for (int i = 0; i < 4; i++) {
        int row = m0 + ty * 4 + i;
        if (row >= Mr) continue;
        #pragma unroll
        for (int j = 0; j < 4; j++) {
            int col = n0 + tx * 4 + j;
            if (col >= N) continue;
            float v = acc[i][j];
            if (bias1) v += bias1[col];
            if (bias2) v += bias2[col];
            if (act == 1)      v = (v > 0.0f) ? v : (expf(v) - 1.0f);
            else if (act == 2) v = (v > 0.0f) ? v : slope * v;
            C[(size_t)row * ldc + col] = v;
        }
    }
}

// ---------------- GAT projections v2: 256x64 tile, 4x16 thread tile ----------------
// A = g_feat [25600 x 42]; B0/B1 = gat weights [42 x 300]; single K pass (pad 48).
#define DU_AS_LD 260
__global__ __launch_bounds__(256) void gemm_dual2(
    const float* __restrict__ A,
    const float* __restrict__ B0, const float* __restrict__ B1,
    float* __restrict__ C0, float* __restrict__ C1,
    const float* __restrict__ bias0, const float* __restrict__ bias1)
{
    extern __shared__ float sm[];
    float* As = sm;                  // [48][260], k-major
    float* Bs = sm + 48 * DU_AS_LD;  // [48][68]
    const int tid = threadIdx.x;
    const int n0 = blockIdx.x * 64;
    const int m0 = blockIdx.y * 256;
    const float* __restrict__ B = blockIdx.z ? B1 : B0;
    float* __restrict__ C = blockIdx.z ? C1 : C0;
    const float* __restrict__ bias = blockIdx.z ? bias1 : bias0;

    #pragma unroll 8
    for (int i = 0; i < 48; i++) {            // A: 256 rows x 48 k
        int idx = tid + 256 * i;
        int k = idx % 48, r = idx / 48;
        float v = (k < 42) ? A[(size_t)(m0 + r) * 42 + k] : 0.0f;
        As[k * DU_AS_LD + r] = v;
    }
    #pragma unroll
    for (int i = 0; i < 12; i++) {            // B: 48 k x 64 cols
        int idx = tid + 256 * i;
        int c = idx & 63, k = idx >> 6;
        float v = 0.0f;
        if (k < 42 && (n0 + c) < HC) v = B[(size_t)k * HC + n0 + c];
        Bs[k * 68 + c] = v;
    }
    __syncthreads();

    const int ty = tid & 63;   // rows ty*4..+3
    const int tx = tid >> 6;   // cols tx*16..+15
    float acc[4][16] = {};
    #pragma unroll 4
    for (int k = 0; k < 48; k++) {
        float4 a = *(const float4*)&As[k * DU_AS_LD + ty * 4];
        float bv[16];
        #pragma unroll
        for (int j = 0; j < 4; j++)
            *(float4*)&bv[4 * j] = *(const float4*)&Bs[k * 68 + tx * 16 + 4 * j];
        float av[4] = {a.x, a.y, a.z, a.w};
        #pragma unroll
        for (int i = 0; i < 4; i++)
            #pragma unroll
            for (int j = 0; j < 16; j++)
                acc[i][j] += av[i] * bv[j];
    }

    #pragma unroll
    for (int i = 0; i < 4; i++) {
        int row = m0 + ty * 4 + i;
        #pragma unroll
        for (int j = 0; j < 16; j++) {
            int col = n0 + tx * 16 + j;
            if (col < HC)
                C[(size_t)row * HC + col] = acc[i][j] + bias[col];
        }
    }
}

// ---------------- LSTM input projection (both dirs, reads past_obs directly) ----------------
__global__ void gemm_lstm(const float* __restrict__ past,
                          const float* __restrict__ Wf, const float* __restrict__ Wb,
                          const float* __restrict__ b1f, const float* __restrict__ b2f,
                          const float* __restrict__ b1b, const float* __restrict__ b2b)
{
    __shared__ float As[16][68];
    __shared__ float Bs[16][64];
    const int tid = threadIdx.x;
    const int m0 = blockIdx.y * 64;
    const int n0 = blockIdx.x * 64;
    const int dir = blockIdx.z;
    const float* __restrict__ B = dir ? Wb : Wf;
    const float* __restrict__ bias1 = dir ? b1b : b1f;
    const float* __restrict__ bias2 = dir ? b2b : b2f;
    const int tx = tid & 15, ty = tid >> 4;
    float acc[4][4] = {};

    for (int k0 = 0; k0 < PASTD; k0 += 16) {
        {
            int ka = k0 + tx;
            #pragma unroll
            for (int it = 0; it < 4; it++) {
                int m = ty + 16 * it;
                int gm = m0 + m;                 // 0..639
                float v = 0.0f;
                if (ka < PASTD) {
                    int t = gm >> 7, bb = gm & 127;
                    int teff = dir ? (Ln - 1 - t) : t;
                    v = past[(bb * Ln + teff) * PASTD + ka];
                }
                As[tx][m] = v;
            }
        }
        {
            int c = tid & 63, kb = tid >> 6;
            #pragma unroll
            for (int it = 0; it < 4; it++) {
                int kk = kb + 4 * it, gk = k0 + kk;
                float v = 0.0f;
                if (gk < PASTD && (n0 + c) < GDIM) v = B[(size_t)gk * GDIM + n0 + c];
                Bs[kk][c] = v;
            }
        }
        __syncthreads();
        #pragma unroll
        for (int k = 0; k < 16; k++) {
            float4 a = *(const float4*)&As[k][ty * 4];
            float4 b = *(const float4*)&Bs[k][tx * 4];
            acc[0][0] += a.x * b.x; acc[0][1] += a.x * b.y; acc[0][2] += a.x * b.z; acc[0][3] += a.x * b.w;
            acc[1][0] += a.y * b.x; acc[1][1] += a.y * b.y; acc[1][2] += a.y * b.z; acc[1][3] += a.y * b.w;
            acc[2][0] += a.z * b.x; acc[2][1] += a.z * b.y; acc[2][2] += a.z * b.z; acc[2][3] += a.z * b.w;
            acc[3][0] += a.w * b.x; acc[3][1] += a.w * b.y; acc[3][2] += a.w * b.z; acc[3][3] += a.w * b.w;
        }
        __syncthreads();
    }

    #pragma unroll
    for (int i = 0; i < 4; i++) {
        int row = m0 + ty * 4 + i;              // < 640 always
        #pragma unroll
        for (int j = 0; j < 4; j++) {
            int col = n0 + tx * 4 + j;
            if (col < GDIM)
                g_gx[(size_t)dir * 640 * GDIM + (size_t)row * GDIM + col] =
                    acc[i][j] + bias1[col] + bias2[col];
        }
    }
}

// ---------------- fused LSTM recurrence: all 5 steps, one launch ----------------
__global__ __launch_bounds__(256) void k_lstm_rec(
    const float* __restrict__ whh_f, const float* __restrict__ whh_b)
{
    const int bid = blockIdx.x;             // 0..79
    const int chunk = bid % 10;
    const int by = (bid / 10) % 4;
    const int dir = bid / 40;
    const float* __restrict__ whh = dir ? whh_b : whh_f;
    const int tid = threadIdx.x;
    __shared__ float h_sh[32][HIDn + 1];

    for (int s = 0; s < Ln; s++) {
        const int b0 = by * 32;
        for (int i = tid; i < 32 * HIDn; i += 256) {
            int bb = i / HIDn, u = i % HIDn;
            h_sh[bb][u] = (s == 0) ? 0.0f
                        : __ldcg(&g_h[(dir * Bn + b0 + bb) * HIDn + u]);
        }
        __syncthreads();
        {
            int col = chunk * 64 + (tid & 63);
            int bi = tid >> 6;
            if (col < GDIM) {               // GUARD: chunk 9 covers cols 576..639, GDIM=600
                float acc[8] = {};
                for (int k = 0; k < HIDn; k++) {
                    float wv = whh[k * GDIM + col];
                    #pragma unroll
                    for (int i = 0; i < 8; i++) acc[i] += h_sh[bi + 4 * i][k] * wv;
                }
                #pragma unroll
                for (int i = 0; i < 8; i++) {
                    int b = b0 + bi + 4 * i;
                    __stcg(&g_gates[(dir * Bn + b) * GDIM + col],
                           g_gx[(size_t)(((dir * Ln + s) * Bn) + b) * GDIM + col] + acc[i]);
                }
            }
        }
        gbar();
        for (int idx = bid * 256 + tid; idx < 2 * Bn * HIDn; idx += NRECB * 256) {
            int d2 = idx / (Bn * HIDn);
            int r = idx % (Bn * HIDn);
            int b = r / HIDn, u = r % HIDn;
            const float* g = &g_gates[(d2 * Bn + b) * GDIM];
            float iv = sigf(__ldcg(&g[u]));
            float fv = sigf(__ldcg(&g[HIDn + u]));
            float gv = tanhf(__ldcg(&g[2 * HIDn + u]));
            float ov = sigf(__ldcg(&g[3 * HIDn + u]));
            float c = (s == 0) ? 0.0f : g_c[idx];
            c = fv * c + iv * gv;
            float h = ov * tanhf(c);
            g_c[idx] = c;
            __stcg(&g_h[idx], h);
            int tout = d2 ? (Ln - 1 - s) : s;
            g_concat[(size_t)b * D2IN + 48100 + tout * HC + d2 * HIDn + u] = h;
        }
        if (s < Ln - 1) gbar();
    }
}

// ---------------- split-K d2 GEMM: one 128x128 block per K-chunk ----------------
__global__ __launch_bounds__(256) void gemm_splitk(const float* __restrict__ A,
                                                   const float* __restrict__ B)
{
    __shared__ float As[16][132];
    __shared__ float Bs[16][132];
    const int tid = threadIdx.x;
    const int z = blockIdx.x;
    const int kbeg = z * CHUNKK;
    const int kend = min(kbeg + CHUNKK, D2IN);
    const int tx = tid & 15, ty = tid >> 4;
    float acc[8][8] = {};

    for (int k0 = kbeg; k0 < kend; k0 += 16) {
        #pragma unroll
        for (int i = 0; i < 8; i++) {
            int idx = tid + 256 * i;
            int r = idx >> 4, kk = idx & 15;
            int gk = k0 + kk;
            As[kk][r] = (gk < kend) ? A[(size_t)r * D2IN + gk] : 0.0f;
        }
        #pragma unroll
        for (int i = 0; i < 8; i++) {
            int idx = tid + 256 * i;
            int c = idx & 127, kk = idx >> 7;
            int gk = k0 + kk;
            Bs[kk][c] = (gk < kend) ? B[(size_t)gk * 128 + c] : 0.0f;
        }
        __syncthreads();
        #pragma unroll
        for (int k = 0; k < 16; k++) {
            float4 a0 = *(const float4*)&As[k][ty * 8];
            float4 a1 = *(const float4*)&As[k][ty * 8 + 4];
            float4 b0 = *(const float4*)&Bs[k][tx * 8];
            float4 b1 = *(const float4*)&Bs[k][tx * 8 + 4];
            float av[8] = {a0.x, a0.y, a0.z, a0.w, a1.x, a1.y, a1.z, a1.w};
            float bv[8] = {b0.x, b0.y, b0.z, b0.w, b1.x, b1.y, b1.z, b1.w};
            #pragma unroll
            for (int i = 0; i < 8; i++)
                #pragma unroll
                for (int j = 0; j < 8; j++)
                    acc[i][j] += av[i] * bv[j];
        }
        __syncthreads();
    }

    float* P = g_partial + (size_t)z * (128 * 128);
    #pragma unroll
    for (int i = 0; i < 8; i++)
        #pragma unroll
        for (int j = 0; j < 8; j++)
            P[(ty * 8 + i) * 128 + tx * 8 + j] = acc[i][j];
}

__global__ void k_d2_reduce_act(const float* __restrict__ d2_b)
{
    int idx = blockIdx.x * 256 + threadIdx.x;
    if (idx >= Bn * 128) return;
    float s = 0.0f;
    #pragma unroll 4
    for (int z = 0; z < SPLITK; z++) s += g_partial[z * (128 * 128) + idx];
    s += d2_b[idx & 127];
    g_hidden[idx] = (s > 0.0f) ? s : (expf(s) - 1.0f);
}

// ---------------- GAT ----------------
__global__ void k_feat(const float* __restrict__ obs)
{
    int idx = blockIdx.x * 256 + threadIdx.x;
    if (idx >= Bn * Mn * 42) return;
    int b = idx / (Mn * 42);
    int r = idx % (Mn * 42);
    int m = r / 42, j = r % 42;
    const float* o = obs + (size_t)b * OBSD;
    float v;
    if (j == 0)       v = o[3 * Mn + 2 + m];
    else if (j == 1)  v = o[4 * Mn + 2 + m];
    else if (j < 22)  v = o[5 * Mn + 2 + m * Sn + (j - 2)];
    else              v = o[5 * Mn + 2 + Mn * Sn + m * Sn + (j - 22)];
    g_feat[idx] = v;
}

// merged CSR build: count + prefix + scatter + per-segment sort (deterministic)
__global__ void k_csr(const int* __restrict__ EI)
{
    __shared__ int tg[ETOT];
    __shared__ int cnt[Mn];
    __shared__ int coff_sh[Mn + 1];
    __shared__ int fill[Mn];
    __shared__ int eid[ETOT];
    int tid = threadIdx.x;
    for (int i = tid; i < Mn; i += 256) { cnt[i] = 0; fill[i] = 0; }
    __syncthreads();
    for (int e = tid; e < ETOT; e += 256) {
        int t = (e < En) ? EI[En + e] : (e - En);
        tg[e] = t;
        atomicAdd(&cnt[t], 1);
    }
    __syncthreads();
    if (tid == 0) {
        int run = 0;
        for (int m = 0; m < Mn; m++) { coff_sh[m] = run; g_coff[m] = run; run += cnt[m]; }
        coff_sh[Mn] = run; g_coff[Mn] = run;
    }
    __syncthreads();
    for (int e = tid; e < ETOT; e += 256) {
        int t = tg[e];
        int pos = coff_sh[t] + atomicAdd(&fill[t], 1);
        eid[pos] = e;
    }
    __syncthreads();
    for (int t = tid; t < Mn; t += 256) {      // stable order via edge-id sort
        int s0 = coff_sh[t], s1 = coff_sh[t + 1];
        for (int i = s0 + 1; i < s1; i++) {
            int v = eid[i];
            int j = i - 1;
            while (j >= s0 && eid[j] > v) { eid[j + 1] = eid[j]; j--; }
            eid[j + 1] = v;
        }
    }
    __syncthreads();
    for (int s = tid; s < ETOT; s += 256) {
        int e = eid[s];
        g_csrc[s] = (e < En) ? EI[e] : (e - En);
    }
}

// Fused GAT attention v3: shuffle-free logits (lane-per-edge, stride-101 smem)
// -> lane-parallel softmax -> channel-parallel aggregation.
// One block per (b, h). Deterministic (CSR order, no atomics).
__global__ __launch_bounds__(256) void k_gat_fused(const float* __restrict__ att,
                                                   const float* __restrict__ gat_bias)
{
    extern __shared__ float sm[];
    float* xl_sh = sm;                 // [Mn][XLD]
    float* xr_sh = sm + Mn * XLD;      // [Mn][XLD]
    __shared__ float lg_sh[ETOT];      // per-slot logits -> weights
    __shared__ float att_sh[Cn];
    int b = blockIdx.x, h = blockIdx.y;
    int tid = threadIdx.x;
    for (int i = tid; i < Mn * Cn; i += 256) {
        int m = i / Cn, c = i % Cn;
        xl_sh[m * XLD + c] = g_xl[((size_t)b * Mn + m) * HC + h * Cn + c];
        xr_sh[m * XLD + c] = g_xr[((size_t)b * Mn + m) * HC + h * Cn + c];
    }
    for (int i = tid; i < Cn; i += 256) att_sh[i] = att[h * Cn + i];
    __syncthreads();

    int w = tid >> 5, lane = tid & 31;
    float bi0 = gat_bias[h * Cn + lane];
    float bi1 = gat_bias[h * Cn + lane + 32];
    float bi2 = gat_bias[h * Cn + lane + 64];
    float bi3 = (lane < 4) ? gat_bias[h * Cn + lane + 96] : 0.0f;

    for (int t = w; t < Mn; t += 8) {
        int s0 = g_coff[t], s1 = g_coff[t + 1];
        int len = s1 - s0;
        const float* xr = &xr_sh[t * XLD];       // broadcast reads (t uniform in warp)

        // ---- pass 1: lane-per-edge logits, no shuffles ----
        for (int base = 0; base < len; base += 32) {
            int sl = base + lane;
            int src = (sl < len) ? g_csrc[s0 + sl] : 0;
            const float* xa = &xl_sh[src * XLD];
            float acc = 0.0f;
            #pragma unroll 4
            for (int c = 0; c < Cn; c++) {
                float v = xa[c] + xr[c];
                v = (v > 0.0f) ? v : 0.2f * v;
                acc = fmaf(v, att_sh[c], acc);
            }
            if (sl < len) lg_sh[s0 + sl] = acc;
        }
        __syncwarp();

        // ---- lane-parallel softmax over lg_sh[s0 .. s1) ----
        float mx = -1e30f;
        for (int off = lane; off < len; off += 32)
            mx = fmaxf(mx, lg_sh[s0 + off]);
        #pragma unroll
        for (int o = 16; o; o >>= 1) mx = fmaxf(mx, __shfl_xor_sync(0xffffffffu, mx, o));
        float den = 0.0f;
        for (int off = lane; off < len; off += 32) {
            float e = expf(lg_sh[s0 + off] - mx);
            lg_sh[s0 + off] = e;
            den += e;
        }
        #pragma unroll
        for (int o = 16; o; o >>= 1) den += __shfl_xor_sync(0xffffffffu, den, o);
        float inv = 1.0f / den;
        __syncwarp();

        // ---- pass 2: channel-parallel aggregation (alpha broadcast, shuffle-free) ----
        float a0 = 0, a1 = 0, a2 = 0, a3 = 0;
        for (int e2 = 0; e2 < len; e2++) {
            float al = lg_sh[s0 + e2] * inv;
            const float* x = &xl_sh[g_csrc[s0 + e2] * XLD];
            a0 += al * x[lane];
            a1 += al * x[lane + 32];
            a2 += al * x[lane + 64];
            if (lane < 4) a3 += al * x[lane + 96];
        }
        float* orow = g_gatout + ((size_t)b * Mn + t) * HC + h * Cn;
        orow[lane]      = a0 + bi0;
        orow[lane + 32] = a1 + bi1;
        orow[lane + 64] = a2 + bi2;
        if (lane < 4) orow[lane + 96] = a3 + bi3;
    }
}

// fused score + top-k pool: one block per batch
__global__ void k_score_topk(const float* __restrict__ pool_w)
{
    __shared__ float pw[HC];
    __shared__ float sc[Mn];
    __shared__ float inv_nrm_sh;
    __shared__ int   sel_idx[Kn];
    __shared__ float sel_val[Kn];
    int b = blockIdx.x, tid = threadIdx.x;
    for (int i = tid; i < HC; i += 256) pw[i] = pool_w[i];
    __syncthreads();
    if (tid < 32) {
        float nw = 0;
        for (int c = tid; c < HC; c += 32) nw += pw[c] * pw[c];
        #pragma unroll
        for (int o = 16; o; o >>= 1) nw += __shfl_xor_sync(0xffffffffu, nw, o);
        if (tid == 0) inv_nrm_sh = rsqrtf(nw);
    }
    __syncthreads();
    float inv_nrm = inv_nrm_sh;
    int w = tid >> 5, lane = tid & 31;
    for (int m = w; m < Mn; m += 8) {
        const float* row = g_gatout + ((size_t)b * Mn + m) * HC;
        float dt = 0;
        for (int c = lane; c < HC; c += 32) dt += row[c] * pw[c];
        #pragma unroll
        for (int o = 16; o; o >>= 1) dt += __shfl_xor_sync(0xffffffffu, dt, o);
        if (lane == 0) sc[m] = tanhf(dt * inv_nrm);
    }
    __syncthreads();
    if (tid < Mn) {
        float sv = sc[tid];
        int rank = 0;
        for (int j = 0; j < Mn; j++) {
            float o = sc[j];
            rank += (o > sv) || (o == sv && j < tid);
        }
        if (rank < Kn) { sel_idx[rank] = tid; sel_val[rank] = sv; }
    }
    __syncthreads();
    for (int idx = tid; idx < Kn * HC; idx += 256) {
        int r = idx / HC, c = idx % HC;
        g_concat[(size_t)b * D2IN + 100 + idx] =
            g_gatout[((size_t)b * Mn + sel_idx[r]) * HC + c] * sel_val[r];
    }
}

// ---------------- launch ----------------
extern "C" void kernel_launch(void* const* d_in, const int* in_sizes, int n_in,
                              void* d_out, int out_size)
{
    const float* obs    = (const float*)d_in[0];
    const float* past   = (const float*)d_in[1];
    const int*   ei     = (const int*)d_in[2];
    const float* d1_w   = (const float*)d_in[3];
    const float* d1_b   = (const float*)d_in[4];
    const float* d2_w   = (const float*)d_in[5];
    const float* d2_b   = (const float*)d_in[6];
    const float* gat_wl = (const float*)d_in[7];
    const float* gat_bl = (const float*)d_in[8];
    const float* gat_wr = (const float*)d_in[9];
    const float* gat_br = (const float*)d_in[10];
    const float* gat_att  = (const float*)d_in[11];
    const float* gat_bias = (const float*)d_in[12];
    const float* pool_w   = (const float*)d_in[13];
    const float* wih_f  = (const float*)d_in[14];
    const float* whh_f  = (const float*)d_in[15];
    const float* bih_f  = (const float*)d_in[16];
    const float* bhh_f  = (const float*)d_in[17];
    const float* wih_b  = (const float*)d_in[18];
    const float* whh_b  = (const float*)d_in[19];
    const float* bih_b  = (const float*)d_in[20];
    const float* bhh_b  = (const float*)d_in[21];
    const float* out_w  = (const float*)d_in[22];
    const float* out_b  = (const float*)d_in[23];
    float* out = (float*)d_out;

    float *p_feat, *p_xl, *p_xr, *p_concat, *p_hidden;
    cudaGetSymbolAddress((void**)&p_feat,   g_feat);
    cudaGetSymbolAddress((void**)&p_xl,     g_xl);
    cudaGetSymbolAddress((void**)&p_xr,     g_xr);
    cudaGetSymbolAddress((void**)&p_concat, g_concat);
    cudaGetSymbolAddress((void**)&p_hidden, g_hidden);

    const int gat_smem = 2 * Mn * XLD * 4;   // 161.6KB dynamic
    cudaFuncSetAttribute(k_gat_fused, cudaFuncAttributeMaxDynamicSharedMemorySize,
                         gat_smem);
    cudaFuncSetAttribute(gemm_dual2, cudaFuncAttributeMaxDynamicSharedMemorySize,
                         (48 * DU_AS_LD + 48 * 68) * 4);

    // launch index 3 (0-based) is the ncu-captured one -> k_gat_fused
    k_csr<<<1, 256>>>(ei);                                                // 0
    k_feat<<<(Bn * Mn * 42 + 255) / 256, 256>>>(obs);                     // 1
    gemm_dual2<<<dim3(5, 100, 2), 256, (48 * DU_AS_LD + 48 * 68) * 4>>>(  // 2
        p_feat, gat_wl, gat_wr, p_xl, p_xr, gat_bl, gat_br);
    k_gat_fused<<<dim3(Bn, Hn), 256, gat_smem>>>(gat_att, gat_bias);      // 3
    k_score_topk<<<Bn, 256>>>(pool_w);                                    // 4

    gemm_lstm<<<dim3(10, 10, 2), 256>>>(past, wih_f, wih_b,               // 5
                                        bih_f, bhh_f, bih_b, bhh_b);
    k_lstm_rec<<<NRECB, 256>>>(whh_f, whh_b);                             // 6

    gemm_bias_act<<<dim3(2, 2), 256>>>(obs, OBSD, d1_w, 100,              // 7
                                       p_concat, D2IN, d1_b, nullptr,
                                       Bn, 100, 3 * Mn + 2, 1, 0.0f);

    gemm_splitk<<<SPLITK, 256>>>(p_concat, d2_w);                         // 8
    k_d2_reduce_act<<<(Bn * 128 + 255) / 256, 256>>>(d2_b);               // 9

    gemm_bias_act<<<dim3(4, 2), 256>>>(p_hidden, 128, out_w, Mn,          // 10
                                       out, Mn, out_b, nullptr,
                                       Bn, Mn, 128, 2, 0.01f);
}

// round 13
// speedup vs baseline: 1.1837x; 1.1837x over previous
#include <cuda_runtime.h>
#include <math.h>
#include <stdint.h>

// ---------------- problem constants ----------------
#define Mn    200
#define Sn    20
#define Hn    3
#define Cn    100
#define Ln    5
#define HIDn  150
#define Bn    128
#define En    3200
#define Kn    160
#define ETOT  3400          // E + M self loops
#define OBSD  9002
#define PASTD 277
#define HC    300           // H*C
#define D2IN  49600
#define GDIM  600           // 4*HID
#define SPLITK 148
#define CHUNKK 336          // 148*336 = 49728 >= 49600
#define NRECB 80            // recurrence blocks (one wave)

// ---------------- scratch (device globals, allocation-free) ----------------
__device__ float g_gx[1280 * GDIM];
__device__ float g_h[2 * Bn * HIDn];
__device__ float g_c[2 * Bn * HIDn];
__device__ float g_gates[2 * Bn * GDIM];
__device__ float g_feat[Bn * Mn * 42];
__device__ float g_xl[Bn * Mn * HC];
__device__ float g_xr[Bn * Mn * HC];
__device__ float g_gatout[Bn * Mn * HC];
__device__ int   g_coff[Mn + 1];
__device__ int   g_csrc[ETOT];
__device__ float g_concat[Bn * D2IN];
__device__ float g_partial[SPLITK * 128 * 128];
__device__ float g_hidden[Bn * 128];
__device__ unsigned g_barc = 0;     // monotonic grid-barrier counter (replay-safe)

// ---------------- helpers ----------------
__device__ __forceinline__ float sigf(float x) { return 1.0f / (1.0f + expf(-x)); }

__device__ __forceinline__ void gbar()
{
    __syncthreads();
    __threadfence();
    if (threadIdx.x == 0) {
        unsigned v = atomicAdd(&g_barc, 1u);
        unsigned target = (v / (unsigned)NRECB + 1u) * (unsigned)NRECB;
        while (atomicAdd(&g_barc, 0u) < target) __nanosleep(64);
    }
    __syncthreads();
}

// ---------------- generic tiled GEMM: C = act(A@B + bias1 + bias2) ----------------
__global__ void gemm_bias_act(const float* __restrict__ A, int lda,
                              const float* __restrict__ B, int ldb,
                              float* __restrict__ C, int ldc,
                              const float* __restrict__ bias1,
                              const float* __restrict__ bias2,
                              int Mr, int N, int Kd, int act, float slope)
{
    __shared__ float As[16][68];
    __shared__ float Bs[16][64];
    const int tid = threadIdx.x;
    const int m0 = blockIdx.y * 64;
    const int n0 = blockIdx.x * 64;
    const int tx = tid & 15;
    const int ty = tid >> 4;
    float acc[4][4] = {};

    for (int k0 = 0; k0 < Kd; k0 += 16) {
        {
            int ka = k0 + tx;
            #pragma unroll
            for (int it = 0; it < 4; it++) {
                int m = ty + 16 * it;
                int gm = m0 + m;
                float v = 0.0f;
                if (gm < Mr && ka < Kd) v = A[(size_t)gm * lda + ka];
                As[tx][m] = v;
            }
        }
        {
            int c = tid & 63;
            int kb = tid >> 6;
            #pragma unroll
            for (int it = 0; it < 4; it++) {
                int kk = kb + 4 * it;
                int gk = k0 + kk;
                float v = 0.0f;
                if (gk < Kd && (n0 + c) < N) v = B[(size_t)gk * ldb + n0 + c];
                Bs[kk][c] = v;
            }
        }
        __syncthreads();
        #pragma unroll
        for (int k = 0; k < 16; k++) {
            float4 a = *(const float4*)&As[k][ty * 4];
            float4 b = *(const float4*)&Bs[k][tx * 4];
            acc[0][0] += a.x * b.x; acc[0][1] += a.x * b.y; acc[0][2] += a.x * b.z; acc[0][3] += a.x * b.w;
            acc[1][0] += a.y * b.x; acc[1][1] += a.y * b.y; acc[1][2] += a.y * b.z; acc[1][3] += a.y * b.w;
            acc[2][0] += a.z * b.x; acc[2][1] += a.z * b.y; acc[2][2] += a.z * b.z; acc[2][3] += a.z * b.w;
            acc[3][0] += a.w * b.x; acc[3][1] += a.w * b.y; acc[3][2] += a.w * b.z; acc[3][3] += a.w * b.w;
        }
        __syncthreads();
    }

    #pragma unroll
    for (int i = 0; i < 4; i++) {
        int row = m0 + ty * 4 + i;
        if (row >= Mr) continue;
        #pragma unroll
        for (int j = 0; j < 4; j++) {
            int col = n0 + tx * 4 + j;
            if (col >= N) continue;
            float v = acc[i][j];
            if (bias1) v += bias1[col];
            if (bias2) v += bias2[col];
            if (act == 1)      v = (v > 0.0f) ? v : (expf(v) - 1.0f);
            else if (act == 2) v = (v > 0.0f) ? v : slope * v;
            C[(size_t)row * ldc + col] = v;
        }
    }
}

// ---------------- GAT projections: 256x64 tile, 4x16 thread tile ----------------
#define DU_AS_LD 260
__global__ __launch_bounds__(256) void gemm_dual2(
    const float* __restrict__ A,
    const float* __restrict__ B0, const float* __restrict__ B1,
    float* __restrict__ C0, float* __restrict__ C1,
    const float* __restrict__ bias0, const float* __restrict__ bias1)
{
    extern __shared__ float sm[];
    float* As = sm;                  // [48][260], k-major
    float* Bs = sm + 48 * DU_AS_LD;  // [48][68]
    const int tid = threadIdx.x;
    const int n0 = blockIdx.x * 64;
    const int m0 = blockIdx.y * 256;
    const float* __restrict__ B = blockIdx.z ? B1 : B0;
    float* __restrict__ C = blockIdx.z ? C1 : C0;
    const float* __restrict__ bias = blockIdx.z ? bias1 : bias0;

    #pragma unroll 8
    for (int i = 0; i < 48; i++) {
        int idx = tid + 256 * i;
        int k = idx % 48, r = idx / 48;
        float v = (k < 42) ? A[(size_t)(m0 + r) * 42 + k] : 0.0f;
        As[k * DU_AS_LD + r] = v;
    }
    #pragma unroll
    for (int i = 0; i < 12; i++) {
        int idx = tid + 256 * i;
        int c = idx & 63, k = idx >> 6;
        float v = 0.0f;
        if (k < 42 && (n0 + c) < HC) v = B[(size_t)k * HC + n0 + c];
        Bs[k * 68 + c] = v;
    }
    __syncthreads();

    const int ty = tid & 63;
    const int tx = tid >> 6;
    float acc[4][16] = {};
    #pragma unroll 4
    for (int k = 0; k < 48; k++) {
        float4 a = *(const float4*)&As[k * DU_AS_LD + ty * 4];
        float bv[16];
        #pragma unroll
        for (int j = 0; j < 4; j++)
            *(float4*)&bv[4 * j] = *(const float4*)&Bs[k * 68 + tx * 16 + 4 * j];
        float av[4] = {a.x, a.y, a.z, a.w};
        #pragma unroll
        for (int i = 0; i < 4; i++)
            #pragma unroll
            for (int j = 0; j < 16; j++)
                acc[i][j] += av[i] * bv[j];
    }

    #pragma unroll
    for (int i = 0; i < 4; i++) {
        int row = m0 + ty * 4 + i;
        #pragma unroll
        for (int j = 0; j < 16; j++) {
            int col = n0 + tx * 16 + j;
            if (col < HC)
                C[(size_t)row * HC + col] = acc[i][j] + bias[col];
        }
    }
}

// ---------------- LSTM input projection (both dirs, reads past_obs directly) ----------------
__global__ void gemm_lstm(const float* __restrict__ past,
                          const float* __restrict__ Wf, const float* __restrict__ Wb,
                          const float* __restrict__ b1f, const float* __restrict__ b2f,
                          const float* __restrict__ b1b, const float* __restrict__ b2b)
{
    __shared__ float As[16][68];
    __shared__ float Bs[16][64];
    const int tid = threadIdx.x;
    const int m0 = blockIdx.y * 64;
    const int n0 = blockIdx.x * 64;
    const int dir = blockIdx.z;
    const float* __restrict__ B = dir ? Wb : Wf;
    const float* __restrict__ bias1 = dir ? b1b : b1f;
    const float* __restrict__ bias2 = dir ? b2b : b2f;
    const int tx = tid & 15, ty = tid >> 4;
    float acc[4][4] = {};

    for (int k0 = 0; k0 < PASTD; k0 += 16) {
        {
            int ka = k0 + tx;
            #pragma unroll
            for (int it = 0; it < 4; it++) {
                int m = ty + 16 * it;
                int gm = m0 + m;                 // 0..639
                float v = 0.0f;
                if (ka < PASTD) {
                    int t = gm >> 7, bb = gm & 127;
                    int teff = dir ? (Ln - 1 - t) : t;
                    v = past[(bb * Ln + teff) * PASTD + ka];
                }
                As[tx][m] = v;
            }
        }
        {
            int c = tid & 63, kb = tid >> 6;
            #pragma unroll
            for (int it = 0; it < 4; it++) {
                int kk = kb + 4 * it, gk = k0 + kk;
                float v = 0.0f;
                if (gk < PASTD && (n0 + c) < GDIM) v = B[(size_t)gk * GDIM + n0 + c];
                Bs[kk][c] = v;
            }
        }
        __syncthreads();
        #pragma unroll
        for (int k = 0; k < 16; k++) {
            float4 a = *(const float4*)&As[k][ty * 4];
            float4 b = *(const float4*)&Bs[k][tx * 4];
            acc[0][0] += a.x * b.x; acc[0][1] += a.x * b.y; acc[0][2] += a.x * b.z; acc[0][3] += a.x * b.w;
            acc[1][0] += a.y * b.x; acc[1][1] += a.y * b.y; acc[1][2] += a.y * b.z; acc[1][3] += a.y * b.w;
            acc[2][0] += a.z * b.x; acc[2][1] += a.z * b.y; acc[2][2] += a.z * b.z; acc[2][3] += a.z * b.w;
            acc[3][0] += a.w * b.x; acc[3][1] += a.w * b.y; acc[3][2] += a.w * b.z; acc[3][3] += a.w * b.w;
        }
        __syncthreads();
    }

    #pragma unroll
    for (int i = 0; i < 4; i++) {
        int row = m0 + ty * 4 + i;
        #pragma unroll
        for (int j = 0; j < 4; j++) {
            int col = n0 + tx * 4 + j;
            if (col < GDIM)
                g_gx[(size_t)dir * 640 * GDIM + (size_t)row * GDIM + col] =
                    acc[i][j] + bias1[col] + bias2[col];
        }
    }
}

// ---------------- fused LSTM recurrence: all 5 steps, one launch ----------------
__global__ __launch_bounds__(256) void k_lstm_rec(
    const float* __restrict__ whh_f, const float* __restrict__ whh_b)
{
    const int bid = blockIdx.x;             // 0..79
    const int chunk = bid % 10;
    const int by = (bid / 10) % 4;
    const int dir = bid / 40;
    const float* __restrict__ whh = dir ? whh_b : whh_f;
    const int tid = threadIdx.x;
    __shared__ float h_sh[32][HIDn + 1];

    for (int s = 0; s < Ln; s++) {
        const int b0 = by * 32;
        for (int i = tid; i < 32 * HIDn; i += 256) {
            int bb = i / HIDn, u = i % HIDn;
            h_sh[bb][u] = (s == 0) ? 0.0f
                        : __ldcg(&g_h[(dir * Bn + b0 + bb) * HIDn + u]);
        }
        __syncthreads();
        {
            int col = chunk * 64 + (tid & 63);
            int bi = tid >> 6;
            if (col < GDIM) {
                float acc[8] = {};
                for (int k = 0; k < HIDn; k++) {
                    float wv = whh[k * GDIM + col];
                    #pragma unroll
                    for (int i = 0; i < 8; i++) acc[i] += h_sh[bi + 4 * i][k] * wv;
                }
                #pragma unroll
                for (int i = 0; i < 8; i++) {
                    int b = b0 + bi + 4 * i;
                    __stcg(&g_gates[(dir * Bn + b) * GDIM + col],
                           g_gx[(size_t)(((dir * Ln + s) * Bn) + b) * GDIM + col] + acc[i]);
                }
            }
        }
        gbar();
        for (int idx = bid * 256 + tid; idx < 2 * Bn * HIDn; idx += NRECB * 256) {
            int d2 = idx / (Bn * HIDn);
            int r = idx % (Bn * HIDn);
            int b = r / HIDn, u = r % HIDn;
            const float* g = &g_gates[(d2 * Bn + b) * GDIM];
            float iv = sigf(__ldcg(&g[u]));
            float fv = sigf(__ldcg(&g[HIDn + u]));
            float gv = tanhf(__ldcg(&g[2 * HIDn + u]));
            float ov = sigf(__ldcg(&g[3 * HIDn + u]));
            float c = (s == 0) ? 0.0f : g_c[idx];
            c = fv * c + iv * gv;
            float h = ov * tanhf(c);
            g_c[idx] = c;
            __stcg(&g_h[idx], h);
            int tout = d2 ? (Ln - 1 - s) : s;
            g_concat[(size_t)b * D2IN + 48100 + tout * HC + d2 * HIDn + u] = h;
        }
        if (s < Ln - 1) gbar();
    }
}

// ---------------- split-K d2 GEMM: one 128x128 block per K-chunk ----------------
__global__ __launch_bounds__(256) void gemm_splitk(const float* __restrict__ A,
                                                   const float* __restrict__ B)
{
    __shared__ float As[16][132];
    __shared__ float Bs[16][132];
    const int tid = threadIdx.x;
    const int z = blockIdx.x;
    const int kbeg = z * CHUNKK;
    const int kend = min(kbeg + CHUNKK, D2IN);
    const int tx = tid & 15, ty = tid >> 4;
    float acc[8][8] = {};

    for (int k0 = kbeg; k0 < kend; k0 += 16) {
        #pragma unroll
        for (int i = 0; i < 8; i++) {
            int idx = tid + 256 * i;
            int r = idx >> 4, kk = idx & 15;
            int gk = k0 + kk;
            As[kk][r] = (gk < kend) ? A[(size_t)r * D2IN + gk] : 0.0f;
        }
        #pragma unroll
        for (int i = 0; i < 8; i++) {
            int idx = tid + 256 * i;
            int c = idx & 127, kk = idx >> 7;
            int gk = k0 + kk;
            Bs[kk][c] = (gk < kend) ? B[(size_t)gk * 128 + c] : 0.0f;
        }
        __syncthreads();
        #pragma unroll
        for (int k = 0; k < 16; k++) {
            float4 a0 = *(const float4*)&As[k][ty * 8];
            float4 a1 = *(const float4*)&As[k][ty * 8 + 4];
            float4 b0 = *(const float4*)&Bs[k][tx * 8];
            float4 b1 = *(const float4*)&Bs[k][tx * 8 + 4];
            float av[8] = {a0.x, a0.y, a0.z, a0.w, a1.x, a1.y, a1.z, a1.w};
            float bv[8] = {b0.x, b0.y, b0.z, b0.w, b1.x, b1.y, b1.z, b1.w};
            #pragma unroll
            for (int i = 0; i < 8; i++)
                #pragma unroll
                for (int j = 0; j < 8; j++)
                    acc[i][j] += av[i] * bv[j];
        }
        __syncthreads();
    }

    float* P = g_partial + (size_t)z * (128 * 128);
    #pragma unroll
    for (int i = 0; i < 8; i++)
        #pragma unroll
        for (int j = 0; j < 8; j++)
            P[(ty * 8 + i) * 128 + tx * 8 + j] = acc[i][j];
}

__global__ void k_d2_reduce_act(const float* __restrict__ d2_b)
{
    int idx = blockIdx.x * 256 + threadIdx.x;
    if (idx >= Bn * 128) return;
    float s = 0.0f;
    #pragma unroll 4
    for (int z = 0; z < SPLITK; z++) s += g_partial[z * (128 * 128) + idx];
    s += d2_b[idx & 127];
    g_hidden[idx] = (s > 0.0f) ? s : (expf(s) - 1.0f);
}

// ---------------- GAT ----------------
__global__ void k_feat(const float* __restrict__ obs)
{
    int idx = blockIdx.x * 256 + threadIdx.x;
    if (idx >= Bn * Mn * 42) return;
    int b = idx / (Mn * 42);
    int r = idx % (Mn * 42);
    int m = r / 42, j = r % 42;
    const float* o = obs + (size_t)b * OBSD;
    float v;
    if (j == 0)       v = o[3 * Mn + 2 + m];
    else if (j == 1)  v = o[4 * Mn + 2 + m];
    else if (j < 22)  v = o[5 * Mn + 2 + m * Sn + (j - 2)];
    else              v = o[5 * Mn + 2 + Mn * Sn + m * Sn + (j - 22)];
    g_feat[idx] = v;
}

// merged CSR build: count + prefix + scatter + per-segment sort (deterministic)
__global__ void k_csr(const int* __restrict__ EI)
{
    __shared__ int tg[ETOT];
    __shared__ int cnt[Mn];
    __shared__ int coff_sh[Mn + 1];
    __shared__ int fill[Mn];
    __shared__ int eid[ETOT];
    int tid = threadIdx.x;
    for (int i = tid; i < Mn; i += 256) { cnt[i] = 0; fill[i] = 0; }
    __syncthreads();
    for (int e = tid; e < ETOT; e += 256) {
        int t = (e < En) ? EI[En + e] : (e - En);
        tg[e] = t;
        atomicAdd(&cnt[t], 1);
    }
    __syncthreads();
    if (tid == 0) {
        int run = 0;
        for (int m = 0; m < Mn; m++) { coff_sh[m] = run; g_coff[m] = run; run += cnt[m]; }
        coff_sh[Mn] = run; g_coff[Mn] = run;
    }
    __syncthreads();
    for (int e = tid; e < ETOT; e += 256) {
        int t = tg[e];
        int pos = coff_sh[t] + atomicAdd(&fill[t], 1);
        eid[pos] = e;
    }
    __syncthreads();
    for (int t = tid; t < Mn; t += 256) {
        int s0 = coff_sh[t], s1 = coff_sh[t + 1];
        for (int i = s0 + 1; i < s1; i++) {
            int v = eid[i];
            int j = i - 1;
            while (j >= s0 && eid[j] > v) { eid[j + 1] = eid[j]; j--; }
            eid[j + 1] = v;
        }
    }
    __syncthreads();
    for (int s = tid; s < ETOT; s += 256) {
        int e = eid[s];
        g_csrc[s] = (e < En) ? EI[e] : (e - En);
    }
}

// Fused GAT attention v4: channel-parallel conflict-free logits with 4-edge ILP
// -> lane-parallel softmax -> channel-parallel aggregation. One block per (b,h).
// Deterministic (CSR order, no atomics).
__global__ __launch_bounds__(256) void k_gat_fused(const float* __restrict__ att,
                                                   const float* __restrict__ gat_bias)
{
    extern __shared__ float xl_sh[];   // Mn*Cn = 20000 floats = 80KB (dynamic)
    __shared__ float lg_sh[ETOT];      // per-slot logits -> weights (13.6KB)
    int b = blockIdx.x, h = blockIdx.y;
    int tid = threadIdx.x;
    for (int i = tid; i < Mn * Cn; i += 256) {
        int m = i / Cn, c = i % Cn;
        xl_sh[i] = g_xl[((size_t)b * Mn + m) * HC + h * Cn + c];
    }
    __syncthreads();

    int w = tid >> 5, lane = tid & 31;
    float attc0 = att[h * Cn + lane];
    float attc1 = att[h * Cn + lane + 32];
    float attc2 = att[h * Cn + lane + 64];
    float attc3 = (lane < 4) ? att[h * Cn + lane + 96] : 0.0f;
    float bi0 = gat_bias[h * Cn + lane];
    float bi1 = gat_bias[h * Cn + lane + 32];
    float bi2 = gat_bias[h * Cn + lane + 64];
    float bi3 = (lane < 4) ? gat_bias[h * Cn + lane + 96] : 0.0f;

    for (int t = w; t < Mn; t += 8) {
        const float* xrr = g_xr + ((size_t)b * Mn + t) * HC + h * Cn;
        float xr0 = xrr[lane], xr1 = xrr[lane + 32], xr2 = xrr[lane + 64];
        float xr3 = (lane < 4) ? xrr[lane + 96] : 0.0f;
        int s0 = g_coff[t], s1 = g_coff[t + 1];
        int len = s1 - s0;

        // ---- pass 1: channel-parallel logits, 4 edges in flight ----
        for (int base = 0; base < len; base += 4) {
            int ne = len - base; if (ne > 4) ne = 4;
            float sacc[4];
            #pragma unroll
            for (int q = 0; q < 4; q++) {
                int sl = (q < ne) ? (base + q) : base;      // clamp (dup, discarded)
                int src = g_csrc[s0 + sl];
                const float* x = &xl_sh[src * Cn];
                float v0 = x[lane] + xr0;       v0 = (v0 > 0.f) ? v0 : 0.2f * v0;
                float v1 = x[lane + 32] + xr1;  v1 = (v1 > 0.f) ? v1 : 0.2f * v1;
                float v2 = x[lane + 64] + xr2;  v2 = (v2 > 0.f) ? v2 : 0.2f * v2;
                float s = v0 * attc0 + v1 * attc1 + v2 * attc2;
                if (lane < 4) {
                    float v3 = x[lane + 96] + xr3; v3 = (v3 > 0.f) ? v3 : 0.2f * v3;
                    s += v3 * attc3;
                }
                sacc[q] = s;
            }
            #pragma unroll
            for (int o = 16; o; o >>= 1) {
                sacc[0] += __shfl_xor_sync(0xffffffffu, sacc[0], o);
                sacc[1] += __shfl_xor_sync(0xffffffffu, sacc[1], o);
                sacc[2] += __shfl_xor_sync(0xffffffffu, sacc[2], o);
                sacc[3] += __shfl_xor_sync(0xffffffffu, sacc[3], o);
            }
            if (lane == 0) {
                #pragma unroll
                for (int q = 0; q < 4; q++)
                    if (q < ne) lg_sh[s0 + base + q] = sacc[q];
            }
        }
        __syncwarp();

        // ---- lane-parallel softmax over lg_sh[s0 .. s1) ----
        float mx = -1e30f;
        for (int off = lane; off < len; off += 32)
            mx = fmaxf(mx, lg_sh[s0 + off]);
        #pragma unroll
        for (int o = 16; o; o >>= 1) mx = fmaxf(mx, __shfl_xor_sync(0xffffffffu, mx, o));
        float den = 0.0f;
        for (int off = lane; off < len; off += 32) {
            float e = expf(lg_sh[s0 + off] - mx);
            lg_sh[s0 + off] = e;
            den += e;
        }
        #pragma unroll
        for (int o = 16; o; o >>= 1) den += __shfl_xor_sync(0xffffffffu, den, o);
        float inv = 1.0f / den;
        __syncwarp();

        // ---- pass 2: channel-parallel aggregation (alpha broadcast, shuffle-free) ----
        float a0 = 0, a1 = 0, a2 = 0, a3 = 0;
        for (int e2 = 0; e2 < len; e2++) {
            float al = lg_sh[s0 + e2] * inv;
            const float* x = &xl_sh[g_csrc[s0 + e2] * Cn];
            a0 += al * x[lane];
            a1 += al * x[lane + 32];
            a2 += al * x[lane + 64];
            if (lane < 4) a3 += al * x[lane + 96];
        }
        float* orow = g_gatout + ((size_t)b * Mn + t) * HC + h * Cn;
        orow[lane]      = a0 + bi0;
        orow[lane + 32] = a1 + bi1;
        orow[lane + 64] = a2 + bi2;
        if (lane < 4) orow[lane + 96] = a3 + bi3;
    }
}

// fused score + top-k pool: one block per batch
__global__ void k_score_topk(const float* __restrict__ pool_w)
{
    __shared__ float pw[HC];
    __shared__ float sc[Mn];
    __shared__ float inv_nrm_sh;
    __shared__ int   sel_idx[Kn];
    __shared__ float sel_val[Kn];
    int b = blockIdx.x, tid = threadIdx.x;
    for (int i = tid; i < HC; i += 256) pw[i] = pool_w[i];
    __syncthreads();
    if (tid < 32) {
        float nw = 0;
        for (int c = tid; c < HC; c += 32) nw += pw[c] * pw[c];
        #pragma unroll
        for (int o = 16; o; o >>= 1) nw += __shfl_xor_sync(0xffffffffu, nw, o);
        if (tid == 0) inv_nrm_sh = rsqrtf(nw);
    }
    __syncthreads();
    float inv_nrm = inv_nrm_sh;
    int w = tid >> 5, lane = tid & 31;
    for (int m = w; m < Mn; m += 8) {
        const float* row = g_gatout + ((size_t)b * Mn + m) * HC;
        float dt = 0;
        for (int c = lane; c < HC; c += 32) dt += row[c] * pw[c];
        #pragma unroll
        for (int o = 16; o; o >>= 1) dt += __shfl_xor_sync(0xffffffffu, dt, o);
        if (lane == 0) sc[m] = tanhf(dt * inv_nrm);
    }
    __syncthreads();
    if (tid < Mn) {
        float sv = sc[tid];
        int rank = 0;
        for (int j = 0; j < Mn; j++) {
            float o = sc[j];
            rank += (o > sv) || (o == sv && j < tid);
        }
        if (rank < Kn) { sel_idx[rank] = tid; sel_val[rank] = sv; }
    }
    __syncthreads();
    for (int idx = tid; idx < Kn * HC; idx += 256) {
        int r = idx / HC, c = idx % HC;
        g_concat[(size_t)b * D2IN + 100 + idx] =
            g_gatout[((size_t)b * Mn + sel_idx[r]) * HC + c] * sel_val[r];
    }
}

// ---------------- launch ----------------
extern "C" void kernel_launch(void* const* d_in, const int* in_sizes, int n_in,
                              void* d_out, int out_size)
{
    const float* obs    = (const float*)d_in[0];
    const float* past   = (const float*)d_in[1];
    const int*   ei     = (const int*)d_in[2];
    const float* d1_w   = (const float*)d_in[3];
    const float* d1_b   = (const float*)d_in[4];
    const float* d2_w   = (const float*)d_in[5];
    const float* d2_b   = (const float*)d_in[6];
    const float* gat_wl = (const float*)d_in[7];
    const float* gat_bl = (const float*)d_in[8];
    const float* gat_wr = (const float*)d_in[9];
    const float* gat_br = (const float*)d_in[10];
    const float* gat_att  = (const float*)d_in[11];
    const float* gat_bias = (const float*)d_in[12];
    const float* pool_w   = (const float*)d_in[13];
    const float* wih_f  = (const float*)d_in[14];
    const float* whh_f  = (const float*)d_in[15];
    const float* bih_f  = (const float*)d_in[16];
    const float* bhh_f  = (const float*)d_in[17];
    const float* wih_b  = (const float*)d_in[18];
    const float* whh_b  = (const float*)d_in[19];
    const float* bih_b  = (const float*)d_in[20];
    const float* bhh_b  = (const float*)d_in[21];
    const float* out_w  = (const float*)d_in[22];
    const float* out_b  = (const float*)d_in[23];
    float* out = (float*)d_out;

    float *p_feat, *p_xl, *p_xr, *p_concat, *p_hidden;
    cudaGetSymbolAddress((void**)&p_feat,   g_feat);
    cudaGetSymbolAddress((void**)&p_xl,     g_xl);
    cudaGetSymbolAddress((void**)&p_xr,     g_xr);
    cudaGetSymbolAddress((void**)&p_concat, g_concat);
    cudaGetSymbolAddress((void**)&p_hidden, g_hidden);

    cudaFuncSetAttribute(k_gat_fused, cudaFuncAttributeMaxDynamicSharedMemorySize,
                         Mn * Cn * 4);
    cudaFuncSetAttribute(gemm_dual2, cudaFuncAttributeMaxDynamicSharedMemorySize,
                         (48 * DU_AS_LD + 48 * 68) * 4);

    // capture window lands on launch index 3 -> k_lstm_rec this round
    k_csr<<<1, 256>>>(ei);                                                // 0
    k_feat<<<(Bn * Mn * 42 + 255) / 256, 256>>>(obs);                     // 1
    gemm_lstm<<<dim3(10, 10, 2), 256>>>(past, wih_f, wih_b,               // 2
                                        bih_f, bhh_f, bih_b, bhh_b);
    k_lstm_rec<<<NRECB, 256>>>(whh_f, whh_b);                             // 3  <- profiled
    gemm_dual2<<<dim3(5, 100, 2), 256, (48 * DU_AS_LD + 48 * 68) * 4>>>(  // 4
        p_feat, gat_wl, gat_wr, p_xl, p_xr, gat_bl, gat_br);
    k_gat_fused<<<dim3(Bn, Hn), 256, Mn * Cn * 4>>>(gat_att, gat_bias);   // 5
    k_score_topk<<<Bn, 256>>>(pool_w);                                    // 6

    gemm_bias_act<<<dim3(2, 2), 256>>>(obs, OBSD, d1_w, 100,              // 7
                                       p_concat, D2IN, d1_b, nullptr,
                                       Bn, 100, 3 * Mn + 2, 1, 0.0f);

    gemm_splitk<<<SPLITK, 256>>>(p_concat, d2_w);                         // 8
    k_d2_reduce_act<<<(Bn * 128 + 255) / 256, 256>>>(d2_b);               // 9

    gemm_bias_act<<<dim3(4, 2), 256>>>(p_hidden, 128, out_w, Mn,          // 10
                                       out, Mn, out_b, nullptr,
                                       Bn, Mn, 128, 2, 0.01f);
}

// round 16
// speedup vs baseline: 1.3095x; 1.1062x over previous
#include <cuda_runtime.h>
#include <math.h>
#include <stdint.h>

// ---------------- problem constants ----------------
#define Mn    200
#define Sn    20
#define Hn    3
#define Cn    100
#define Ln    5
#define HIDn  150
#define Bn    128
#define En    3200
#define Kn    160
#define ETOT  3400          // E + M self loops
#define OBSD  9002
#define PASTD 277
#define HC    300           // H*C
#define D2IN  49600
#define GDIM  600           // 4*HID
#define SPLITK 148
#define CHUNKK 336          // 148*336 = 49728 >= 49600
#define NRECB 80            // recurrence blocks (one wave)

// dynamic smem partition for k_lstm_rec (floats)
#define REC_WHH_OFF 0                    // [HIDn][60]        9000
#define REC_H_OFF   (REC_WHH_OFF + HIDn * 60)          // [32][152]  4864
#define REC_GT_OFF  (REC_H_OFF + 32 * 152)             // [32][60]   1920
#define REC_C_OFF   (REC_GT_OFF + 32 * 60)             // [32][15]    480
#define REC_SMEM_FLOATS (REC_C_OFF + 32 * 15)          // 16264 floats = 65056 B

// ---------------- scratch (device globals, allocation-free) ----------------
__device__ float g_gx[1280 * GDIM];
__device__ float g_hbuf[2 * 2 * Bn * HIDn];   // double-buffered h
__device__ float g_feat[Bn * Mn * 42];
__device__ float g_xl[Bn * Mn * HC];
__device__ float g_xr[Bn * Mn * HC];
__device__ float g_gatout[Bn * Mn * HC];
__device__ int   g_coff[Mn + 1];
__device__ int   g_csrc[ETOT];
__device__ float g_concat[Bn * D2IN];
__device__ float g_partial[SPLITK * 128 * 128];
__device__ float g_hidden[Bn * 128];
__device__ unsigned g_barc = 0;     // monotonic grid-barrier counter (replay-safe)

// ---------------- helpers ----------------
__device__ __forceinline__ float sigf(float x) { return 1.0f / (1.0f + expf(-x)); }

__device__ __forceinline__ void gbar()
{
    __syncthreads();
    __threadfence();
    if (threadIdx.x == 0) {
        unsigned v = atomicAdd(&g_barc, 1u);
        unsigned target = (v / (unsigned)NRECB + 1u) * (unsigned)NRECB;
        while (atomicAdd(&g_barc, 0u) < target) __nanosleep(64);
    }
    __syncthreads();
}

// ---------------- generic tiled GEMM: C = act(A@B + bias1 + bias2) ----------------
__global__ void gemm_bias_act(const float* __restrict__ A, int lda,
                              const float* __restrict__ B, int ldb,
                              float* __restrict__ C, int ldc,
                              const float* __restrict__ bias1,
                              const float* __restrict__ bias2,
                              int Mr, int N, int Kd, int act, float slope)
{
    __shared__ float As[16][68];
    __shared__ float Bs[16][64];
    const int tid = threadIdx.x;
    const int m0 = blockIdx.y * 64;
    const int n0 = blockIdx.x * 64;
    const int tx = tid & 15;
    const int ty = tid >> 4;
    float acc[4][4] = {};

    for (int k0 = 0; k0 < Kd; k0 += 16) {
        {
            int ka = k0 + tx;
            #pragma unroll
            for (int it = 0; it < 4; it++) {
                int m = ty + 16 * it;
                int gm = m0 + m;
                float v = 0.0f;
                if (gm < Mr && ka < Kd) v = A[(size_t)gm * lda + ka];
                As[tx][m] = v;
            }
        }
        {
            int c = tid & 63;
            int kb = tid >> 6;
            #pragma unroll
            for (int it = 0; it < 4; it++) {
                int kk = kb + 4 * it;
                int gk = k0 + kk;
                float v = 0.0f;
                if (gk < Kd && (n0 + c) < N) v = B[(size_t)gk * ldb + n0 + c];
                Bs[kk][c] = v;
            }
        }
        __syncthreads();
        #pragma unroll
        for (int k = 0; k < 16; k++) {
            float4 a = *(const float4*)&As[k][ty * 4];
            float4 b = *(const float4*)&Bs[k][tx * 4];
            acc[0][0] += a.x * b.x; acc[0][1] += a.x * b.y; acc[0][2] += a.x * b.z; acc[0][3] += a.x * b.w;
            acc[1][0] += a.y * b.x; acc[1][1] += a.y * b.y; acc[1][2] += a.y * b.z; acc[1][3] += a.y * b.w;
            acc[2][0] += a.z * b.x; acc[2][1] += a.z * b.y; acc[2][2] += a.z * b.z; acc[2][3] += a.z * b.w;
            acc[3][0] += a.w * b.x; acc[3][1] += a.w * b.y; acc[3][2] += a.w * b.z; acc[3][3] += a.w * b.w;
        }
        __syncthreads();
    }

    #pragma unroll
    for (int i = 0; i < 4; i++) {
        int row = m0 + ty * 4 + i;
        if (row >= Mr) continue;
        #pragma unroll
        for (int j = 0; j < 4; j++) {
            int col = n0 + tx * 4 + j;
            if (col >= N) continue;
            float v = acc[i][j];
            if (bias1) v += bias1[col];
            if (bias2) v += bias2[col];
            if (act == 1)      v = (v > 0.0f) ? v : (expf(v) - 1.0f);
            else if (act == 2) v = (v > 0.0f) ? v : slope * v;
            C[(size_t)row * ldc + col] = v;
        }
    }
}

// ---------------- GAT projections: 256x64 tile, 4x16 thread tile ----------------
#define DU_AS_LD 260
__global__ __launch_bounds__(256) void gemm_dual2(
    const float* __restrict__ A,
    const float* __restrict__ B0, const float* __restrict__ B1,
    float* __restrict__ C0, float* __restrict__ C1,
    const float* __restrict__ bias0, const float* __restrict__ bias1)
{
    extern __shared__ float sm[];
    float* As = sm;                  // [48][260], k-major
    float* Bs = sm + 48 * DU_AS_LD;  // [48][68]
    const int tid = threadIdx.x;
    const int n0 = blockIdx.x * 64;
    const int m0 = blockIdx.y * 256;
    const float* __restrict__ B = blockIdx.z ? B1 : B0;
    float* __restrict__ C = blockIdx.z ? C1 : C0;
    const float* __restrict__ bias = blockIdx.z ? bias1 : bias0;

    #pragma unroll 8
    for (int i = 0; i < 48; i++) {
        int idx = tid + 256 * i;
        int k = idx % 48, r = idx / 48;
        float v = (k < 42) ? A[(size_t)(m0 + r) * 42 + k] : 0.0f;
        As[k * DU_AS_LD + r] = v;
    }
    #pragma unroll
    for (int i = 0; i < 12; i++) {
        int idx = tid + 256 * i;
        int c = idx & 63, k = idx >> 6;
        float v = 0.0f;
        if (k < 42 && (n0 + c) < HC) v = B[(size_t)k * HC + n0 + c];
        Bs[k * 68 + c] = v;
    }
    __syncthreads();

    const int ty = tid & 63;
    const int tx = tid >> 6;
    float acc[4][16] = {};
    #pragma unroll 4
    for (int k = 0; k < 48; k++) {
        float4 a = *(const float4*)&As[k * DU_AS_LD + ty * 4];
        float bv[16];
        #pragma unroll
        for (int j = 0; j < 4; j++)
            *(float4*)&bv[4 * j] = *(const float4*)&Bs[k * 68 + tx * 16 + 4 * j];
        float av[4] = {a.x, a.y, a.z, a.w};
        #pragma unroll
        for (int i = 0; i < 4; i++)
            #pragma unroll
            for (int j = 0; j < 16; j++)
                acc[i][j] += av[i] * bv[j];
    }

    #pragma unroll
    for (int i = 0; i < 4; i++) {
        int row = m0 + ty * 4 + i;
        #pragma unroll
        for (int j = 0; j < 16; j++) {
            int col = n0 + tx * 16 + j;
            if (col < HC)
                C[(size_t)row * HC + col] = acc[i][j] + bias[col];
        }
    }
}

// ---------------- LSTM input projection (both dirs, reads past_obs directly) ----------------
__global__ void gemm_lstm(const float* __restrict__ past,
                          const float* __restrict__ Wf, const float* __restrict__ Wb,
                          const float* __restrict__ b1f, const float* __restrict__ b2f,
                          const float* __restrict__ b1b, const float* __restrict__ b2b)
{
    __shared__ float As[16][68];
    __shared__ float Bs[16][64];
    const int tid = threadIdx.x;
    const int m0 = blockIdx.y * 64;
    const int n0 = blockIdx.x * 64;
    const int dir = blockIdx.z;
    const float* __restrict__ B = dir ? Wb : Wf;
    const float* __restrict__ bias1 = dir ? b1b : b1f;
    const float* __restrict__ bias2 = dir ? b2b : b2f;
    const int tx = tid & 15, ty = tid >> 4;
    float acc[4][4] = {};

    for (int k0 = 0; k0 < PASTD; k0 += 16) {
        {
            int ka = k0 + tx;
            #pragma unroll
            for (int it = 0; it < 4; it++) {
                int m = ty + 16 * it;
                int gm = m0 + m;                 // 0..639
                float v = 0.0f;
                if (ka < PASTD) {
                    int t = gm >> 7, bb = gm & 127;
                    int teff = dir ? (Ln - 1 - t) : t;
                    v = past[(bb * Ln + teff) * PASTD + ka];
                }
                As[tx][m] = v;
            }
        }
        {
            int c = tid & 63, kb = tid >> 6;
            #pragma unroll
            for (int it = 0; it < 4; it++) {
                int kk = kb + 4 * it, gk = k0 + kk;
                float v = 0.0f;
                if (gk < PASTD && (n0 + c) < GDIM) v = B[(size_t)gk * GDIM + n0 + c];
                Bs[kk][c] = v;
            }
        }
        __syncthreads();
        #pragma unroll
        for (int k = 0; k < 16; k++) {
            float4 a = *(const float4*)&As[k][ty * 4];
            float4 b = *(const float4*)&Bs[k][tx * 4];
            acc[0][0] += a.x * b.x; acc[0][1] += a.x * b.y; acc[0][2] += a.x * b.z; acc[0][3] += a.x * b.w;
            acc[1][0] += a.y * b.x; acc[1][1] += a.y * b.y; acc[1][2] += a.y * b.z; acc[1][3] += a.y * b.w;
            acc[2][0] += a.z * b.x; acc[2][1] += a.z * b.y; acc[2][2] += a.z * b.z; acc[2][3] += a.z * b.w;
            acc[3][0] += a.w * b.x; acc[3][1] += a.w * b.y; acc[3][2] += a.w * b.z; acc[3][3] += a.w * b.w;
        }
        __syncthreads();
    }

    #pragma unroll
    for (int i = 0; i < 4; i++) {
        int row = m0 + ty * 4 + i;
        #pragma unroll
        for (int j = 0; j < 4; j++) {
            int col = n0 + tx * 4 + j;
            if (col < GDIM)
                g_gx[(size_t)dir * 640 * GDIM + (size_t)row * GDIM + col] =
                    acc[i][j] + bias1[col] + bias2[col];
        }
    }
}

// ---------------- fused LSTM recurrence v2 (dynamic smem) ----------------
// Block = (dir, batch-tile 32, unit-chunk 15). Each block computes ALL 4 gates
// for its cells (whh slice preloaded to smem), updates c/h locally, writes h to
// a double-buffered global. Only 1 grid barrier per step boundary (4 total).
__global__ __launch_bounds__(256) void k_lstm_rec(
    const float* __restrict__ whh_f, const float* __restrict__ whh_b)
{
    extern __shared__ float rsm[];
    float* whh_sh = rsm + REC_WHH_OFF;    // [HIDn][60]
    float* h_sh   = rsm + REC_H_OFF;      // [32][152]
    float* gt_sh  = rsm + REC_GT_OFF;     // [32][60]
    float* c_sh   = rsm + REC_C_OFF;      // [32][15]

    const int bid = blockIdx.x;           // 0..79
    const int dir = bid / 40;
    const int by  = (bid % 40) / 10;      // 4 batch tiles of 32
    const int uc  = bid % 10;             // 10 unit chunks of 15
    const int u0  = uc * 15;
    const int b0  = by * 32;
    const int tid = threadIdx.x;
    const float* __restrict__ whh = dir ? whh_b : whh_f;

    for (int i = tid; i < HIDn * 60; i += 256) {
        int k = i / 60, j = i % 60;
        int g = j / 15, u = j % 15;
        whh_sh[k * 60 + j] = whh[k * GDIM + g * HIDn + u0 + u];
    }
    for (int i = tid; i < 32 * 15; i += 256) c_sh[i] = 0.0f;
    __syncthreads();

    for (int s = 0; s < Ln; s++) {
        const int rb = (s - 1) & 1;                 // read buffer (s>0)
        const int wb = s & 1;                       // write buffer
        for (int i = tid; i < 32 * HIDn; i += 256) {
            int bb = i / HIDn, u = i % HIDn;
            h_sh[bb * 152 + u] = (s == 0) ? 0.0f
                : __ldcg(&g_hbuf[rb * (2 * Bn * HIDn) + (dir * Bn + b0 + bb) * HIDn + u]);
        }
        __syncthreads();
        {
            int gc = tid & 63;      // 0..63 (60 active)
            int bq = tid >> 6;      // 0..3
            if (gc < 60) {
                int g = gc / 15, u = gc % 15;
                int col = g * HIDn + u0 + u;
                float acc[8] = {};
                for (int k = 0; k < HIDn; k++) {
                    float wv = whh_sh[k * 60 + gc];
                    #pragma unroll
                    for (int i = 0; i < 8; i++) acc[i] += h_sh[(bq + 4 * i) * 152 + k] * wv;
                }
                #pragma unroll
                for (int i = 0; i < 8; i++) {
                    int bb = bq + 4 * i;
                    gt_sh[bb * 60 + gc] = acc[i] +
                        g_gx[(size_t)(((dir * Ln + s) * Bn) + b0 + bb) * GDIM + col];
                }
            }
        }
        __syncthreads();
        for (int i = tid; i < 32 * 15; i += 256) {
            int bb = i / 15, u = i % 15;
            float iv = sigf(gt_sh[bb * 60 + u]);
            float fv = sigf(gt_sh[bb * 60 + 15 + u]);
            float gv = tanhf(gt_sh[bb * 60 + 30 + u]);
            float ov = sigf(gt_sh[bb * 60 + 45 + u]);
            float c = fv * c_sh[bb * 15 + u] + iv * gv;
            float hh = ov * tanhf(c);
            c_sh[bb * 15 + u] = c;
            __stcg(&g_hbuf[wb * (2 * Bn * HIDn) + (dir * Bn + b0 + bb) * HIDn + u0 + u], hh);
            int tout = dir ? (Ln - 1 - s) : s;
            g_concat[(size_t)(b0 + bb) * D2IN + 48100 + tout * HC + dir * HIDn + u0 + u] = hh;
        }
        if (s < Ln - 1) gbar();
    }
}

// ---------------- split-K d2 GEMM: one 128x128 block per K-chunk ----------------
__global__ __launch_bounds__(256) void gemm_splitk(const float* __restrict__ A,
                                                   const float* __restrict__ B)
{
    __shared__ float As[16][132];
    __shared__ float Bs[16][132];
    const int tid = threadIdx.x;
    const int z = blockIdx.x;
    const int kbeg = z * CHUNKK;
    const int kend = min(kbeg + CHUNKK, D2IN);
    const int tx = tid & 15, ty = tid >> 4;
    float acc[8][8] = {};

    for (int k0 = kbeg; k0 < kend; k0 += 16) {
        #pragma unroll
        for (int i = 0; i < 8; i++) {
            int idx = tid + 256 * i;
            int r = idx >> 4, kk = idx & 15;
            int gk = k0 + kk;
            As[kk][r] = (gk < kend) ? A[(size_t)r * D2IN + gk] : 0.0f;
        }
        #pragma unroll
        for (int i = 0; i < 8; i++) {
            int idx = tid + 256 * i;
            int c = idx & 127, kk = idx >> 7;
            int gk = k0 + kk;
            Bs[kk][c] = (gk < kend) ? B[(size_t)gk * 128 + c] : 0.0f;
        }
        __syncthreads();
        #pragma unroll
        for (int k = 0; k < 16; k++) {
            float4 a0 = *(const float4*)&As[k][ty * 8];
            float4 a1 = *(const float4*)&As[k][ty * 8 + 4];
            float4 b0 = *(const float4*)&Bs[k][tx * 8];
            float4 b1 = *(const float4*)&Bs[k][tx * 8 + 4];
            float av[8] = {a0.x, a0.y, a0.z, a0.w, a1.x, a1.y, a1.z, a1.w};
            float bv[8] = {b0.x, b0.y, b0.z, b0.w, b1.x, b1.y, b1.z, b1.w};
            #pragma unroll
            for (int i = 0; i < 8; i++)
                #pragma unroll
                for (int j = 0; j < 8; j++)
                    acc[i][j] += av[i] * bv[j];
        }
        __syncthreads();
    }

    float* P = g_partial + (size_t)z * (128 * 128);
    #pragma unroll
    for (int i = 0; i < 8; i++)
        #pragma unroll
        for (int j = 0; j < 8; j++)
            P[(ty * 8 + i) * 128 + tx * 8 + j] = acc[i][j];
}

__global__ void k_d2_reduce_act(const float* __restrict__ d2_b)
{
    int idx = blockIdx.x * 256 + threadIdx.x;
    if (idx >= Bn * 128) return;
    float s = 0.0f;
    #pragma unroll 4
    for (int z = 0; z < SPLITK; z++) s += g_partial[z * (128 * 128) + idx];
    s += d2_b[idx & 127];
    g_hidden[idx] = (s > 0.0f) ? s : (expf(s) - 1.0f);
}

// ---------------- GAT ----------------
__global__ void k_feat(const float* __restrict__ obs)
{
    int idx = blockIdx.x * 256 + threadIdx.x;
    if (idx >= Bn * Mn * 42) return;
    int b = idx / (Mn * 42);
    int r = idx % (Mn * 42);
    int m = r / 42, j = r % 42;
    const float* o = obs + (size_t)b * OBSD;
    float v;
    if (j == 0)       v = o[3 * Mn + 2 + m];
    else if (j == 1)  v = o[4 * Mn + 2 + m];
    else if (j < 22)  v = o[5 * Mn + 2 + m * Sn + (j - 2)];
    else              v = o[5 * Mn + 2 + Mn * Sn + m * Sn + (j - 22)];
    g_feat[idx] = v;
}

// merged CSR build: count + prefix + scatter + per-segment sort (deterministic)
__global__ void k_csr(const int* __restrict__ EI)
{
    __shared__ int tg[ETOT];
    __shared__ int cnt[Mn];
    __shared__ int coff_sh[Mn + 1];
    __shared__ int fill[Mn];
    __shared__ int eid[ETOT];
    int tid = threadIdx.x;
    for (int i = tid; i < Mn; i += 256) { cnt[i] = 0; fill[i] = 0; }
    __syncthreads();
    for (int e = tid; e < ETOT; e += 256) {
        int t = (e < En) ? EI[En + e] : (e - En);
        tg[e] = t;
        atomicAdd(&cnt[t], 1);
    }
    __syncthreads();
    if (tid == 0) {
        int run = 0;
        for (int m = 0; m < Mn; m++) { coff_sh[m] = run; g_coff[m] = run; run += cnt[m]; }
        coff_sh[Mn] = run; g_coff[Mn] = run;
    }
    __syncthreads();
    for (int e = tid; e < ETOT; e += 256) {
        int t = tg[e];
        int pos = coff_sh[t] + atomicAdd(&fill[t], 1);
        eid[pos] = e;
    }
    __syncthreads();
    for (int t = tid; t < Mn; t += 256) {
        int s0 = coff_sh[t], s1 = coff_sh[t + 1];
        for (int i = s0 + 1; i < s1; i++) {
            int v = eid[i];
            int j = i - 1;
            while (j >= s0 && eid[j] > v) { eid[j + 1] = eid[j]; j--; }
            eid[j + 1] = v;
        }
    }
    __syncthreads();
    for (int s = tid; s < ETOT; s += 256) {
        int e = eid[s];
        g_csrc[s] = (e < En) ? EI[e] : (e - En);
    }
}

// Fused GAT attention v4: channel-parallel conflict-free logits with 4-edge ILP
// -> lane-parallel softmax -> channel-parallel aggregation. One block per (b,h).
__global__ __launch_bounds__(256) void k_gat_fused(const float* __restrict__ att,
                                                   const float* __restrict__ gat_bias)
{
    extern __shared__ float xl_sh[];   // Mn*Cn = 20000 floats = 80KB (dynamic)
    __shared__ float lg_sh[ETOT];      // per-slot logits -> weights (13.6KB)
    int b = blockIdx.x, h = blockIdx.y;
    int tid = threadIdx.x;
    for (int i = tid; i < Mn * Cn; i += 256) {
        int m = i / Cn, c = i % Cn;
        xl_sh[i] = g_xl[((size_t)b * Mn + m) * HC + h * Cn + c];
    }
    __syncthreads();

    int w = tid >> 5, lane = tid & 31;
    float attc0 = att[h * Cn + lane];
    float attc1 = att[h * Cn + lane + 32];
    float attc2 = att[h * Cn + lane + 64];
    float attc3 = (lane < 4) ? att[h * Cn + lane + 96] : 0.0f;
    float bi0 = gat_bias[h * Cn + lane];
    float bi1 = gat_bias[h * Cn + lane + 32];
    float bi2 = gat_bias[h * Cn + lane + 64];
    float bi3 = (lane < 4) ? gat_bias[h * Cn + lane + 96] : 0.0f;

    for (int t = w; t < Mn; t += 8) {
        const float* xrr = g_xr + ((size_t)b * Mn + t) * HC + h * Cn;
        float xr0 = xrr[lane], xr1 = xrr[lane + 32], xr2 = xrr[lane + 64];
        float xr3 = (lane < 4) ? xrr[lane + 96] : 0.0f;
        int s0 = g_coff[t], s1 = g_coff[t + 1];
        int len = s1 - s0;

        for (int base = 0; base < len; base += 4) {
            int ne = len - base; if (ne > 4) ne = 4;
            float sacc[4];
            #pragma unroll
            for (int q = 0; q < 4; q++) {
                int sl = (q < ne) ? (base + q) : base;
                int src = g_csrc[s0 + sl];
                const float* x = &xl_sh[src * Cn];
                float v0 = x[lane] + xr0;       v0 = (v0 > 0.f) ? v0 : 0.2f * v0;
                float v1 = x[lane + 32] + xr1;  v1 = (v1 > 0.f) ? v1 : 0.2f * v1;
                float v2 = x[lane + 64] + xr2;  v2 = (v2 > 0.f) ? v2 : 0.2f * v2;
                float s = v0 * attc0 + v1 * attc1 + v2 * attc2;
                if (lane < 4) {
                    float v3 = x[lane + 96] + xr3; v3 = (v3 > 0.f) ? v3 : 0.2f * v3;
                    s += v3 * attc3;
                }
                sacc[q] = s;
            }
            #pragma unroll
            for (int o = 16; o; o >>= 1) {
                sacc[0] += __shfl_xor_sync(0xffffffffu, sacc[0], o);
                sacc[1] += __shfl_xor_sync(0xffffffffu, sacc[1], o);
                sacc[2] += __shfl_xor_sync(0xffffffffu, sacc[2], o);
                sacc[3] += __shfl_xor_sync(0xffffffffu, sacc[3], o);
            }
            if (lane == 0) {
                #pragma unroll
                for (int q = 0; q < 4; q++)
                    if (q < ne) lg_sh[s0 + base + q] = sacc[q];
            }
        }
        __syncwarp();

        float mx = -1e30f;
        for (int off = lane; off < len; off += 32)
            mx = fmaxf(mx, lg_sh[s0 + off]);
        #pragma unroll
        for (int o = 16; o; o >>= 1) mx = fmaxf(mx, __shfl_xor_sync(0xffffffffu, mx, o));
        float den = 0.0f;
        for (int off = lane; off < len; off += 32) {
            float e = expf(lg_sh[s0 + off] - mx);
            lg_sh[s0 + off] = e;
            den += e;
        }
        #pragma unroll
        for (int o = 16; o; o >>= 1) den += __shfl_xor_sync(0xffffffffu, den, o);
        float inv = 1.0f / den;
        __syncwarp();

        float a0 = 0, a1 = 0, a2 = 0, a3 = 0;
        for (int e2 = 0; e2 < len; e2++) {
            float al = lg_sh[s0 + e2] * inv;
            const float* x = &xl_sh[g_csrc[s0 + e2] * Cn];
            a0 += al * x[lane];
            a1 += al * x[lane + 32];
            a2 += al * x[lane + 64];
            if (lane < 4) a3 += al * x[lane + 96];
        }
        float* orow = g_gatout + ((size_t)b * Mn + t) * HC + h * Cn;
        orow[lane]      = a0 + bi0;
        orow[lane + 32] = a1 + bi1;
        orow[lane + 64] = a2 + bi2;
        if (lane < 4) orow[lane + 96] = a3 + bi3;
    }
}

// fused score + top-k pool: one block per batch
__global__ void k_score_topk(const float* __restrict__ pool_w)
{
    __shared__ float pw[HC];
    __shared__ float sc[Mn];
    __shared__ float inv_nrm_sh;
    __shared__ int   sel_idx[Kn];
    __shared__ float sel_val[Kn];
    int b = blockIdx.x, tid = threadIdx.x;
    for (int i = tid; i < HC; i += 256) pw[i] = pool_w[i];
    __syncthreads();
    if (tid < 32) {
        float nw = 0;
        for (int c = tid; c < HC; c += 32) nw += pw[c] * pw[c];
        #pragma unroll
        for (int o = 16; o; o >>= 1) nw += __shfl_xor_sync(0xffffffffu, nw, o);
        if (tid == 0) inv_nrm_sh = rsqrtf(nw);
    }
    __syncthreads();
    float inv_nrm = inv_nrm_sh;
    int w = tid >> 5, lane = tid & 31;
    for (int m = w; m < Mn; m += 8) {
        const float* row = g_gatout + ((size_t)b * Mn + m) * HC;
        float dt = 0;
        for (int c = lane; c < HC; c += 32) dt += row[c] * pw[c];
        #pragma unroll
        for (int o = 16; o; o >>= 1) dt += __shfl_xor_sync(0xffffffffu, dt, o);
        if (lane == 0) sc[m] = tanhf(dt * inv_nrm);
    }
    __syncthreads();
    if (tid < Mn) {
        float sv = sc[tid];
        int rank = 0;
        for (int j = 0; j < Mn; j++) {
            float o = sc[j];
            rank += (o > sv) || (o == sv && j < tid);
        }
        if (rank < Kn) { sel_idx[rank] = tid; sel_val[rank] = sv; }
    }
    __syncthreads();
    for (int idx = tid; idx < Kn * HC; idx += 256) {
        int r = idx / HC, c = idx % HC;
        g_concat[(size_t)b * D2IN + 100 + idx] =
            g_gatout[((size_t)b * Mn + sel_idx[r]) * HC + c] * sel_val[r];
    }
}

// ---------------- launch ----------------
extern "C" void kernel_launch(void* const* d_in, const int* in_sizes, int n_in,
                              void* d_out, int out_size)
{
    const float* obs    = (const float*)d_in[0];
    const float* past   = (const float*)d_in[1];
    const int*   ei     = (const int*)d_in[2];
    const float* d1_w   = (const float*)d_in[3];
    const float* d1_b   = (const float*)d_in[4];
    const float* d2_w   = (const float*)d_in[5];
    const float* d2_b   = (const float*)d_in[6];
    const float* gat_wl = (const float*)d_in[7];
    const float* gat_bl = (const float*)d_in[8];
    const float* gat_wr = (const float*)d_in[9];
    const float* gat_br = (const float*)d_in[10];
    const float* gat_att  = (const float*)d_in[11];
    const float* gat_bias = (const float*)d_in[12];
    const float* pool_w   = (const float*)d_in[13];
    const float* wih_f  = (const float*)d_in[14];
    const float* whh_f  = (const float*)d_in[15];
    const float* bih_f  = (const float*)d_in[16];
    const float* bhh_f  = (const float*)d_in[17];
    const float* wih_b  = (const float*)d_in[18];
    const float* whh_b  = (const float*)d_in[19];
    const float* bih_b  = (const float*)d_in[20];
    const float* bhh_b  = (const float*)d_in[21];
    const float* out_w  = (const float*)d_in[22];
    const float* out_b  = (const float*)d_in[23];
    float* out = (float*)d_out;

    float *p_feat, *p_xl, *p_xr, *p_concat, *p_hidden;
    cudaGetSymbolAddress((void**)&p_feat,   g_feat);
    cudaGetSymbolAddress((void**)&p_xl,     g_xl);
    cudaGetSymbolAddress((void**)&p_xr,     g_xr);
    cudaGetSymbolAddress((void**)&p_concat, g_concat);
    cudaGetSymbolAddress((void**)&p_hidden, g_hidden);

    const int rec_smem = REC_SMEM_FLOATS * 4;      // 65056 bytes
    cudaFuncSetAttribute(k_gat_fused, cudaFuncAttributeMaxDynamicSharedMemorySize,
                         Mn * Cn * 4);
    cudaFuncSetAttribute(gemm_dual2, cudaFuncAttributeMaxDynamicSharedMemorySize,
                         (48 * DU_AS_LD + 48 * 68) * 4);
    cudaFuncSetAttribute(k_lstm_rec, cudaFuncAttributeMaxDynamicSharedMemorySize,
                         rec_smem);

    // capture window lands on launch index 3 -> k_lstm_rec (verify the fix)
    k_csr<<<1, 256>>>(ei);                                                // 0
    k_feat<<<(Bn * Mn * 42 + 255) / 256, 256>>>(obs);                     // 1
    gemm_lstm<<<dim3(10, 10, 2), 256>>>(past, wih_f, wih_b,               // 2
                                        bih_f, bhh_f, bih_b, bhh_b);
    k_lstm_rec<<<NRECB, 256, rec_smem>>>(whh_f, whh_b);                   // 3  <- profiled
    gemm_dual2<<<dim3(5, 100, 2), 256, (48 * DU_AS_LD + 48 * 68) * 4>>>(  // 4
        p_feat, gat_wl, gat_wr, p_xl, p_xr, gat_bl, gat_br);
    k_gat_fused<<<dim3(Bn, Hn), 256, Mn * Cn * 4>>>(gat_att, gat_bias);   // 5
    k_score_topk<<<Bn, 256>>>(pool_w);                                    // 6

    gemm_bias_act<<<dim3(2, 2), 256>>>(obs, OBSD, d1_w, 100,              // 7
                                       p_concat, D2IN, d1_b, nullptr,
                                       Bn, 100, 3 * Mn + 2, 1, 0.0f);

    gemm_splitk<<<SPLITK, 256>>>(p_concat, d2_w);                         // 8
    k_d2_reduce_act<<<(Bn * 128 + 255) / 256, 256>>>(d2_b);               // 9

    gemm_bias_act<<<dim3(4, 2), 256>>>(p_hidden, 128, out_w, Mn,          // 10
                                       out, Mn, out_b, nullptr,
                                       Bn, Mn, 128, 2, 0.01f);
}